// round 3
// baseline (speedup 1.0000x reference)
#include <cuda_runtime.h>
#include <cuda_bf16.h>
#include <math.h>

#define BB 2
#define QLEN 1024
#define MLEN 1024
#define KLEN 2048
#define EE 1024
#define HH 16
#define DH 64
#define HD 1024   // HH*DH
#define FF 4096

// ---------------- scratch ----------------
static __device__ float g_cat[(size_t)BB * KLEN * EE];
static __device__ float g_q  [(size_t)BB * QLEN * HD];
static __device__ float g_k  [(size_t)BB * KLEN * HD];
static __device__ float g_v  [(size_t)BB * KLEN * HD];
static __device__ float g_r  [(size_t)KLEN * HD];
static __device__ float g_att[(size_t)BB * QLEN * HD];
static __device__ float g_o  [(size_t)BB * QLEN * EE];
static __device__ float g_x  [(size_t)BB * QLEN * EE];
static __device__ float g_ffn[(size_t)BB * QLEN * FF];
static __device__ float g_y  [(size_t)BB * QLEN * EE];

// ---------------- helpers ----------------
__device__ __forceinline__ unsigned f2t(float x) {
    unsigned u; asm("cvt.rna.tf32.f32 %0, %1;" : "=r"(u) : "f"(x)); return u;
}
__device__ __forceinline__ void mma8(float* c, const unsigned* a, const unsigned* b) {
    asm volatile("mma.sync.aligned.m16n8k8.row.col.f32.tf32.tf32.f32 "
        "{%0,%1,%2,%3}, {%4,%5,%6,%7}, {%8,%9}, {%0,%1,%2,%3};\n"
        : "+f"(c[0]), "+f"(c[1]), "+f"(c[2]), "+f"(c[3])
        : "r"(a[0]), "r"(a[1]), "r"(a[2]), "r"(a[3]), "r"(b[0]), "r"(b[1]));
}

// ---------------- cat = concat(member, w) ----------------
__global__ __launch_bounds__(256) void copy_cat_kernel(
    const float4* __restrict__ w, const float4* __restrict__ member, float4* __restrict__ cat)
{
    size_t i = (size_t)blockIdx.x * 256 + threadIdx.x;
    int e4 = (int)(i % (EE / 4));
    size_t t2 = i / (EE / 4);
    int kl = (int)(t2 % KLEN);
    int b  = (int)(t2 / KLEN);
    float4 v;
    if (kl < MLEN) v = member[((size_t)b * MLEN + kl) * (EE / 4) + e4];
    else           v = w[((size_t)b * QLEN + (kl - MLEN)) * (EE / 4) + e4];
    cat[i] = v;
}

// ================= tf32 MMA GEMM, NN (same as R2, proven) =================
__global__ __launch_bounds__(256, 2) void gemm_nn_tf32(
    const float* __restrict__ A, int lda, const float* __restrict__ B, int ldb,
    float* __restrict__ C, int ldc, int N, int K, int relu)
{
    __shared__ __align__(16) unsigned As[2][128][20];
    __shared__ __align__(16) unsigned Bs[2][16][136];

    const int t = threadIdx.x;
    const int lane = t & 31, warp = t >> 5;
    const int g = lane >> 2, tig = lane & 3;
    const int wm0 = (warp >> 2) * 64, wn0 = (warp & 3) * 32;
    const int m0 = blockIdx.y * 128, n0 = blockIdx.x * 128;

    const int arow = t >> 2,  akc = (t & 3) * 4;
    const int brow = t >> 5,  bnc = (t & 31) * 4;

    float c[4][4][4] = {};

    {
        #pragma unroll
        for (int j = 0; j < 2; j++) {
            int row = arow + 64 * j;
            float4 f = *(const float4*)&A[(size_t)(m0 + row) * lda + akc];
            As[0][row][akc + 0] = f2t(f.x); As[0][row][akc + 1] = f2t(f.y);
            As[0][row][akc + 2] = f2t(f.z); As[0][row][akc + 3] = f2t(f.w);
        }
        #pragma unroll
        for (int j = 0; j < 2; j++) {
            int row = brow + 8 * j;
            int n = n0 + bnc;
            float4 f = make_float4(0.f, 0.f, 0.f, 0.f);
            if (n < N) f = *(const float4*)&B[(size_t)row * ldb + n];
            Bs[0][row][bnc + 0] = f2t(f.x); Bs[0][row][bnc + 1] = f2t(f.y);
            Bs[0][row][bnc + 2] = f2t(f.z); Bs[0][row][bnc + 3] = f2t(f.w);
        }
    }
    __syncthreads();

    const int nk = K / 16;
    int buf = 0;
    for (int kt = 0; kt < nk; kt++) {
        float4 ra[2], rb[2];
        if (kt + 1 < nk) {
            int k0 = (kt + 1) * 16;
            #pragma unroll
            for (int j = 0; j < 2; j++)
                ra[j] = *(const float4*)&A[(size_t)(m0 + arow + 64 * j) * lda + k0 + akc];
            #pragma unroll
            for (int j = 0; j < 2; j++) {
                int n = n0 + bnc;
                rb[j] = make_float4(0.f, 0.f, 0.f, 0.f);
                if (n < N) rb[j] = *(const float4*)&B[(size_t)(k0 + brow + 8 * j) * ldb + n];
            }
        }
        #pragma unroll
        for (int ks = 0; ks < 16; ks += 8) {
            unsigned af[4][4], bf[4][2];
            #pragma unroll
            for (int mi = 0; mi < 4; mi++) {
                int m = wm0 + mi * 16 + g;
                af[mi][0] = As[buf][m][ks + tig];
                af[mi][1] = As[buf][m + 8][ks + tig];
                af[mi][2] = As[buf][m][ks + tig + 4];
                af[mi][3] = As[buf][m + 8][ks + tig + 4];
            }
            #pragma unroll
            for (int ni = 0; ni < 4; ni++) {
                int n = wn0 + ni * 8 + g;
                bf[ni][0] = Bs[buf][ks + tig][n];
                bf[ni][1] = Bs[buf][ks + tig + 4][n];
            }
            #pragma unroll
            for (int mi = 0; mi < 4; mi++)
                #pragma unroll
                for (int ni = 0; ni < 4; ni++)
                    mma8(c[mi][ni], af[mi], bf[ni]);
        }
        if (kt + 1 < nk) {
            int nb = buf ^ 1;
            #pragma unroll
            for (int j = 0; j < 2; j++) {
                int row = arow + 64 * j;
                As[nb][row][akc + 0] = f2t(ra[j].x); As[nb][row][akc + 1] = f2t(ra[j].y);
                As[nb][row][akc + 2] = f2t(ra[j].z); As[nb][row][akc + 3] = f2t(ra[j].w);
            }
            #pragma unroll
            for (int j = 0; j < 2; j++) {
                int row = brow + 8 * j;
                Bs[nb][row][bnc + 0] = f2t(rb[j].x); Bs[nb][row][bnc + 1] = f2t(rb[j].y);
                Bs[nb][row][bnc + 2] = f2t(rb[j].z); Bs[nb][row][bnc + 3] = f2t(rb[j].w);
            }
            __syncthreads();
        }
        buf ^= 1;
    }

    #pragma unroll
    for (int mi = 0; mi < 4; mi++) {
        int row = m0 + wm0 + mi * 16 + g;
        #pragma unroll
        for (int ni = 0; ni < 4; ni++) {
            int col = n0 + wn0 + ni * 8 + 2 * tig;
            if (col < N) {
                float2 v0 = make_float2(c[mi][ni][0], c[mi][ni][1]);
                float2 v1 = make_float2(c[mi][ni][2], c[mi][ni][3]);
                if (relu) {
                    v0.x = fmaxf(v0.x, 0.f); v0.y = fmaxf(v0.y, 0.f);
                    v1.x = fmaxf(v1.x, 0.f); v1.y = fmaxf(v1.y, 0.f);
                }
                *(float2*)&C[(size_t)row * ldc + col] = v0;
                *(float2*)&C[(size_t)(row + 8) * ldc + col] = v1;
            }
        }
    }
}

// ================= fused flash attention with rel-shift =================
// Block: (b, h, q-tile 128). Loops k-tiles of 128. Per tile:
//   AC = (Q+rwb) @ K^T  (tf32 MMA)
//   BD via two G tiles: G[qi,c] = (Q+rrb) @ Rh[j0+c]^T, c in [0,256); gather c=127+ki-qi
//   online softmax, P@V accumulated into O regs.
#define FA_SMEM (4*34816 + 67584 + 2048)
__global__ __launch_bounds__(256, 1) void flash_attn(
    const float* __restrict__ Qm, const float* __restrict__ Km,
    const float* __restrict__ Vm, const float* __restrict__ Rm,
    const float* __restrict__ rwb, const float* __restrict__ rrb,
    float* __restrict__ Om)
{
    extern __shared__ __align__(16) char smem[];
    unsigned (*sQw)[68]  = (unsigned(*)[68])(smem);
    unsigned (*sQr)[68]  = (unsigned(*)[68])(smem + 34816);
    unsigned (*sB )[68]  = (unsigned(*)[68])(smem + 2 * 34816);
    unsigned (*sV )[68]  = (unsigned(*)[68])(smem + 3 * 34816);
    float    (*sG )[132] = (float(*)[132]) (smem + 4 * 34816);
    float    *sRed       = (float*)(smem + 4 * 34816 + 67584);

    const int t = threadIdx.x;
    const int lane = t & 31, warp = t >> 5;
    const int g = lane >> 2, tig = lane & 3;
    const int wm0 = (warp >> 2) * 64;
    const int wn  = warp & 3;
    const int wn0 = wn * 32;
    const int wn0p = wn * 16;

    const int bh = blockIdx.z, b = bh >> 4, h = bh & 15;
    const int q0 = blockIdx.y * 128;

    const int lr = t >> 1, lc0 = (t & 1) * 32;

    // load Q tile with both biases
    {
        const float* qsrc = Qm + ((size_t)b * QLEN + q0) * HD + h * DH;
        #pragma unroll
        for (int i = 0; i < 8; i++) {
            int c = lc0 + i * 4;
            float4 f  = *(const float4*)&qsrc[(size_t)lr * HD + c];
            float4 bw = *(const float4*)&rwb[h * DH + c];
            float4 br = *(const float4*)&rrb[h * DH + c];
            sQw[lr][c+0] = f2t(f.x + bw.x); sQw[lr][c+1] = f2t(f.y + bw.y);
            sQw[lr][c+2] = f2t(f.z + bw.z); sQw[lr][c+3] = f2t(f.w + bw.w);
            sQr[lr][c+0] = f2t(f.x + br.x); sQr[lr][c+1] = f2t(f.y + br.y);
            sQr[lr][c+2] = f2t(f.z + br.z); sQr[lr][c+3] = f2t(f.w + br.w);
        }
    }

    float o[4][2][4] = {};
    float mrun[4][2], lrun[4][2];
    #pragma unroll
    for (int mi = 0; mi < 4; mi++)
        #pragma unroll
        for (int hh = 0; hh < 2; hh++) { mrun[mi][hh] = -INFINITY; lrun[mi][hh] = 0.f; }

    const int ntiles = q0 / 128 + 9;    // causal: k <= q + MLEN
    for (int kt = 0; kt < ntiles; kt++) {
        const int k0 = kt * 128;
        const int j0 = k0 - q0 + (QLEN - 128);   // Rh band base; >= 0 always

        // ---- load K, V tiles ----
        {
            const float* ksrc = Km + ((size_t)b * KLEN + k0) * HD + h * DH;
            const float* vsrc = Vm + ((size_t)b * KLEN + k0) * HD + h * DH;
            #pragma unroll
            for (int i = 0; i < 8; i++) {
                int c = lc0 + i * 4;
                float4 f = *(const float4*)&ksrc[(size_t)lr * HD + c];
                sB[lr][c+0] = f2t(f.x); sB[lr][c+1] = f2t(f.y);
                sB[lr][c+2] = f2t(f.z); sB[lr][c+3] = f2t(f.w);
                float4 v = *(const float4*)&vsrc[(size_t)lr * HD + c];
                sV[lr][c+0] = f2t(v.x); sV[lr][c+1] = f2t(v.y);
                sV[lr][c+2] = f2t(v.z); sV[lr][c+3] = f2t(v.w);
            }
        }
        __syncthreads();

        // ---- AC MMA (NT): acc = (Q+rwb) @ K^T ----
        float acc[4][4][4] = {};
        #pragma unroll
        for (int ks = 0; ks < 64; ks += 8) {
            unsigned af[4][4], bf[4][2];
            #pragma unroll
            for (int mi = 0; mi < 4; mi++) {
                int m = wm0 + mi * 16 + g;
                af[mi][0] = sQw[m][ks + tig];     af[mi][1] = sQw[m + 8][ks + tig];
                af[mi][2] = sQw[m][ks + tig + 4]; af[mi][3] = sQw[m + 8][ks + tig + 4];
            }
            #pragma unroll
            for (int ni = 0; ni < 4; ni++) {
                int n = wn0 + ni * 8 + g;
                bf[ni][0] = sB[n][ks + tig]; bf[ni][1] = sB[n][ks + tig + 4];
            }
            #pragma unroll
            for (int mi = 0; mi < 4; mi++)
                #pragma unroll
                for (int ni = 0; ni < 4; ni++)
                    mma8(acc[mi][ni], af[mi], bf[ni]);
        }
        __syncthreads();   // sB free

        // ---- load Rh tile 1 (rows j0 .. j0+127, clamped) ----
        {
            int jr = j0 + lr; if (jr > KLEN - 1) jr = KLEN - 1;
            const float* rsrc = Rm + (size_t)jr * HD + h * DH;
            #pragma unroll
            for (int i = 0; i < 8; i++) {
                int c = lc0 + i * 4;
                float4 f = *(const float4*)&rsrc[c];
                sB[lr][c+0] = f2t(f.x); sB[lr][c+1] = f2t(f.y);
                sB[lr][c+2] = f2t(f.z); sB[lr][c+3] = f2t(f.w);
            }
        }
        __syncthreads();

        // ---- G phase 1 ----
        {
            float gacc[4][4][4] = {};
            #pragma unroll
            for (int ks = 0; ks < 64; ks += 8) {
                unsigned af[4][4], bf[4][2];
                #pragma unroll
                for (int mi = 0; mi < 4; mi++) {
                    int m = wm0 + mi * 16 + g;
                    af[mi][0] = sQr[m][ks + tig];     af[mi][1] = sQr[m + 8][ks + tig];
                    af[mi][2] = sQr[m][ks + tig + 4]; af[mi][3] = sQr[m + 8][ks + tig + 4];
                }
                #pragma unroll
                for (int ni = 0; ni < 4; ni++) {
                    int n = wn0 + ni * 8 + g;
                    bf[ni][0] = sB[n][ks + tig]; bf[ni][1] = sB[n][ks + tig + 4];
                }
                #pragma unroll
                for (int mi = 0; mi < 4; mi++)
                    #pragma unroll
                    for (int ni = 0; ni < 4; ni++)
                        mma8(gacc[mi][ni], af[mi], bf[ni]);
            }
            #pragma unroll
            for (int mi = 0; mi < 4; mi++)
                #pragma unroll
                for (int ni = 0; ni < 4; ni++)
                    #pragma unroll
                    for (int hh = 0; hh < 2; hh++) {
                        int r = wm0 + mi * 16 + g + 8 * hh;
                        int col = wn0 + ni * 8 + 2 * tig;
                        sG[r][col]     = gacc[mi][ni][2 * hh];
                        sG[r][col + 1] = gacc[mi][ni][2 * hh + 1];
                    }
        }
        __syncthreads();   // sG(G1) ready; sB reads done

        // ---- load Rh tile 2 (overlaps gather) ----
        {
            int jr = j0 + 128 + lr; if (jr > KLEN - 1) jr = KLEN - 1;
            const float* rsrc = Rm + (size_t)jr * HD + h * DH;
            #pragma unroll
            for (int i = 0; i < 8; i++) {
                int c = lc0 + i * 4;
                float4 f = *(const float4*)&rsrc[c];
                sB[lr][c+0] = f2t(f.x); sB[lr][c+1] = f2t(f.y);
                sB[lr][c+2] = f2t(f.z); sB[lr][c+3] = f2t(f.w);
            }
        }
        // ---- gather phase 1 (c < 128) ----
        #pragma unroll
        for (int mi = 0; mi < 4; mi++)
            #pragma unroll
            for (int ni = 0; ni < 4; ni++)
                #pragma unroll
                for (int hh = 0; hh < 2; hh++)
                    #pragma unroll
                    for (int e = 0; e < 2; e++) {
                        int r = wm0 + mi * 16 + g + 8 * hh;
                        int col = wn0 + ni * 8 + 2 * tig + e;
                        int c = 127 + col - r;
                        if (c < 128) acc[mi][ni][2 * hh + e] += sG[r][c];
                    }
        __syncthreads();   // R2 visible, sG free

        // ---- G phase 2 ----
        {
            float gacc[4][4][4] = {};
            #pragma unroll
            for (int ks = 0; ks < 64; ks += 8) {
                unsigned af[4][4], bf[4][2];
                #pragma unroll
                for (int mi = 0; mi < 4; mi++) {
                    int m = wm0 + mi * 16 + g;
                    af[mi][0] = sQr[m][ks + tig];     af[mi][1] = sQr[m + 8][ks + tig];
                    af[mi][2] = sQr[m][ks + tig + 4]; af[mi][3] = sQr[m + 8][ks + tig + 4];
                }
                #pragma unroll
                for (int ni = 0; ni < 4; ni++) {
                    int n = wn0 + ni * 8 + g;
                    bf[ni][0] = sB[n][ks + tig]; bf[ni][1] = sB[n][ks + tig + 4];
                }
                #pragma unroll
                for (int mi = 0; mi < 4; mi++)
                    #pragma unroll
                    for (int ni = 0; ni < 4; ni++)
                        mma8(gacc[mi][ni], af[mi], bf[ni]);
            }
            #pragma unroll
            for (int mi = 0; mi < 4; mi++)
                #pragma unroll
                for (int ni = 0; ni < 4; ni++)
                    #pragma unroll
                    for (int hh = 0; hh < 2; hh++) {
                        int r = wm0 + mi * 16 + g + 8 * hh;
                        int col = wn0 + ni * 8 + 2 * tig;
                        sG[r][col]     = gacc[mi][ni][2 * hh];
                        sG[r][col + 1] = gacc[mi][ni][2 * hh + 1];
                    }
        }
        __syncthreads();

        // ---- gather phase 2 + mask + scale ----
        #pragma unroll
        for (int mi = 0; mi < 4; mi++)
            #pragma unroll
            for (int ni = 0; ni < 4; ni++)
                #pragma unroll
                for (int hh = 0; hh < 2; hh++)
                    #pragma unroll
                    for (int e = 0; e < 2; e++) {
                        int r = wm0 + mi * 16 + g + 8 * hh;
                        int col = wn0 + ni * 8 + 2 * tig + e;
                        int c = 127 + col - r;
                        float s = acc[mi][ni][2 * hh + e];
                        if (c >= 128) s += sG[r][c - 128];
                        s = ((k0 + col) <= (q0 + r) + MLEN) ? s * 0.03125f : -1e30f;
                        acc[mi][ni][2 * hh + e] = s;
                    }

        // ---- online softmax ----
        float tval[4][2];
        #pragma unroll
        for (int mi = 0; mi < 4; mi++)
            #pragma unroll
            for (int hh = 0; hh < 2; hh++) {
                float m8 = fmaxf(fmaxf(acc[mi][0][2*hh], acc[mi][0][2*hh+1]),
                                 fmaxf(acc[mi][1][2*hh], acc[mi][1][2*hh+1]));
                m8 = fmaxf(m8, fmaxf(fmaxf(acc[mi][2][2*hh], acc[mi][2][2*hh+1]),
                                     fmaxf(acc[mi][3][2*hh], acc[mi][3][2*hh+1])));
                m8 = fmaxf(m8, __shfl_xor_sync(0xffffffffu, m8, 1));
                m8 = fmaxf(m8, __shfl_xor_sync(0xffffffffu, m8, 2));
                tval[mi][hh] = m8;
            }
        if (tig == 0) {
            #pragma unroll
            for (int mi = 0; mi < 4; mi++)
                #pragma unroll
                for (int hh = 0; hh < 2; hh++)
                    sRed[wn * 128 + wm0 + mi * 16 + g + 8 * hh] = tval[mi][hh];
        }
        __syncthreads();
        float mnew[4][2];
        #pragma unroll
        for (int mi = 0; mi < 4; mi++)
            #pragma unroll
            for (int hh = 0; hh < 2; hh++) {
                int r = wm0 + mi * 16 + g + 8 * hh;
                float mm = fmaxf(fmaxf(sRed[r], sRed[128 + r]),
                                 fmaxf(sRed[256 + r], sRed[384 + r]));
                mnew[mi][hh] = fmaxf(mrun[mi][hh], mm);
            }
        __syncthreads();   // sRed reuse

        #pragma unroll
        for (int mi = 0; mi < 4; mi++)
            #pragma unroll
            for (int hh = 0; hh < 2; hh++) {
                float s = 0.f;
                #pragma unroll
                for (int ni = 0; ni < 4; ni++)
                    #pragma unroll
                    for (int e = 0; e < 2; e++) {
                        float p = __expf(acc[mi][ni][2 * hh + e] - mnew[mi][hh]);
                        acc[mi][ni][2 * hh + e] = p;
                        s += p;
                    }
                s += __shfl_xor_sync(0xffffffffu, s, 1);
                s += __shfl_xor_sync(0xffffffffu, s, 2);
                tval[mi][hh] = s;
            }
        if (tig == 0) {
            #pragma unroll
            for (int mi = 0; mi < 4; mi++)
                #pragma unroll
                for (int hh = 0; hh < 2; hh++)
                    sRed[wn * 128 + wm0 + mi * 16 + g + 8 * hh] = tval[mi][hh];
        }
        __syncthreads();
        #pragma unroll
        for (int mi = 0; mi < 4; mi++)
            #pragma unroll
            for (int hh = 0; hh < 2; hh++) {
                int r = wm0 + mi * 16 + g + 8 * hh;
                float ls = sRed[r] + sRed[128 + r] + sRed[256 + r] + sRed[384 + r];
                float alpha = __expf(mrun[mi][hh] - mnew[mi][hh]);
                lrun[mi][hh] = lrun[mi][hh] * alpha + ls;
                mrun[mi][hh] = mnew[mi][hh];
                #pragma unroll
                for (int ni2 = 0; ni2 < 2; ni2++) {
                    o[mi][ni2][2 * hh]     *= alpha;
                    o[mi][ni2][2 * hh + 1] *= alpha;
                }
            }

        // ---- write P (tf32) into sG ----
        #pragma unroll
        for (int mi = 0; mi < 4; mi++)
            #pragma unroll
            for (int ni = 0; ni < 4; ni++)
                #pragma unroll
                for (int hh = 0; hh < 2; hh++) {
                    int r = wm0 + mi * 16 + g + 8 * hh;
                    int col = wn0 + ni * 8 + 2 * tig;
                    sG[r][col]     = __uint_as_float(f2t(acc[mi][ni][2 * hh]));
                    sG[r][col + 1] = __uint_as_float(f2t(acc[mi][ni][2 * hh + 1]));
                }
        __syncthreads();

        // ---- PV MMA (NN): O += P @ V ----
        #pragma unroll
        for (int ks = 0; ks < 128; ks += 8) {
            unsigned af[4][4], bf[2][2];
            #pragma unroll
            for (int mi = 0; mi < 4; mi++) {
                int m = wm0 + mi * 16 + g;
                af[mi][0] = __float_as_uint(sG[m][ks + tig]);
                af[mi][1] = __float_as_uint(sG[m + 8][ks + tig]);
                af[mi][2] = __float_as_uint(sG[m][ks + tig + 4]);
                af[mi][3] = __float_as_uint(sG[m + 8][ks + tig + 4]);
            }
            #pragma unroll
            for (int ni2 = 0; ni2 < 2; ni2++) {
                int n = wn0p + ni2 * 8 + g;
                bf[ni2][0] = sV[ks + tig][n];
                bf[ni2][1] = sV[ks + tig + 4][n];
            }
            #pragma unroll
            for (int mi = 0; mi < 4; mi++)
                #pragma unroll
                for (int ni2 = 0; ni2 < 2; ni2++)
                    mma8(o[mi][ni2], af[mi], bf[ni2]);
        }
        __syncthreads();   // before next tile overwrites sG/sB/sV
    }

    // ---- epilogue: O /= l ----
    #pragma unroll
    for (int mi = 0; mi < 4; mi++)
        #pragma unroll
        for (int ni2 = 0; ni2 < 2; ni2++)
            #pragma unroll
            for (int hh = 0; hh < 2; hh++) {
                int r = wm0 + mi * 16 + g + 8 * hh;
                int d = wn0p + ni2 * 8 + 2 * tig;
                float inv = 1.0f / lrun[mi][hh];
                float2 val = make_float2(o[mi][ni2][2 * hh] * inv,
                                         o[mi][ni2][2 * hh + 1] * inv);
                *(float2*)&Om[((size_t)b * QLEN + q0 + r) * HD + h * DH + d] = val;
            }
}

// ---------------- out = LayerNorm(a + b), rows of EE ----------------
__global__ __launch_bounds__(256) void add_ln_kernel(
    const float* __restrict__ A, const float* __restrict__ Bv,
    const float* __restrict__ gamma, const float* __restrict__ beta,
    float* __restrict__ out)
{
    __shared__ float red[256];
    const size_t row = blockIdx.x;
    const int t = threadIdx.x;
    float4 va = ((const float4*)(A + row * EE))[t];
    float4 vb = ((const float4*)(Bv + row * EE))[t];
    float4 v = make_float4(va.x + vb.x, va.y + vb.y, va.z + vb.z, va.w + vb.w);

    red[t] = v.x + v.y + v.z + v.w; __syncthreads();
    for (int s = 128; s > 0; s >>= 1) { if (t < s) red[t] += red[t + s]; __syncthreads(); }
    const float mean = red[0] * (1.0f / EE); __syncthreads();

    float dx = v.x - mean, dy = v.y - mean, dz = v.z - mean, dw = v.w - mean;
    red[t] = dx * dx + dy * dy + dz * dz + dw * dw; __syncthreads();
    for (int s = 128; s > 0; s >>= 1) { if (t < s) red[t] += red[t + s]; __syncthreads(); }
    const float inv = rsqrtf(red[0] * (1.0f / EE) + 1e-3f);

    float4 gm = ((const float4*)gamma)[t];
    float4 bt = ((const float4*)beta)[t];
    float4 o;
    o.x = dx * inv * gm.x + bt.x; o.y = dy * inv * gm.y + bt.y;
    o.z = dz * inv * gm.z + bt.z; o.w = dw * inv * gm.w + bt.w;
    ((float4*)(out + row * EE))[t] = o;
}

// ---------------- launch ----------------
extern "C" void kernel_launch(void* const* d_in, const int* in_sizes, int n_in,
                              void* d_out, int out_size)
{
    const float* w      = (const float*)d_in[0];
    const float* r      = (const float*)d_in[1];
    const float* member = (const float*)d_in[2];
    const float* Wq  = (const float*)d_in[4];
    const float* Wk  = (const float*)d_in[5];
    const float* Wv  = (const float*)d_in[6];
    const float* Wr  = (const float*)d_in[7];
    const float* Wo  = (const float*)d_in[8];
    const float* rwb = (const float*)d_in[9];
    const float* rrb = (const float*)d_in[10];
    const float* ln1g = (const float*)d_in[11];
    const float* ln1b = (const float*)d_in[12];
    const float* W1  = (const float*)d_in[13];
    const float* W2  = (const float*)d_in[14];
    const float* ln2g = (const float*)d_in[15];
    const float* ln2b = (const float*)d_in[16];
    float* out = (float*)d_out;

    static float *p_cat = nullptr, *p_q, *p_k, *p_v, *p_r,
                 *p_att, *p_o, *p_x, *p_ffn, *p_y;
    if (!p_cat) {
        cudaGetSymbolAddress((void**)&p_cat, g_cat);
        cudaGetSymbolAddress((void**)&p_q,   g_q);
        cudaGetSymbolAddress((void**)&p_k,   g_k);
        cudaGetSymbolAddress((void**)&p_v,   g_v);
        cudaGetSymbolAddress((void**)&p_r,   g_r);
        cudaGetSymbolAddress((void**)&p_att, g_att);
        cudaGetSymbolAddress((void**)&p_o,   g_o);
        cudaGetSymbolAddress((void**)&p_x,   g_x);
        cudaGetSymbolAddress((void**)&p_ffn, g_ffn);
        cudaGetSymbolAddress((void**)&p_y,   g_y);
        cudaFuncSetAttribute(flash_attn, cudaFuncAttributeMaxDynamicSharedMemorySize, FA_SMEM);
    }

    // 1. cat
    copy_cat_kernel<<<(BB * KLEN * EE / 4) / 256, 256>>>(
        (const float4*)w, (const float4*)member, (float4*)p_cat);

    // 2. projections (tf32 MMA)
    gemm_nn_tf32<<<dim3(HD / 128, (BB * QLEN) / 128), 256>>>(w,     EE, Wq, HD, p_q, HD, HD, EE, 0);
    gemm_nn_tf32<<<dim3(HD / 128, (BB * KLEN) / 128), 256>>>(p_cat, EE, Wk, HD, p_k, HD, HD, EE, 0);
    gemm_nn_tf32<<<dim3(HD / 128, (BB * KLEN) / 128), 256>>>(p_cat, EE, Wv, HD, p_v, HD, HD, EE, 0);
    gemm_nn_tf32<<<dim3(HD / 128, KLEN / 128),        256>>>(r,     EE, Wr, HD, p_r, HD, HD, EE, 0);

    // 3. fused attention (AC + shifted BD + softmax + PV)
    flash_attn<<<dim3(1, QLEN / 128, BB * HH), 256, FA_SMEM>>>(
        p_q, p_k, p_v, p_r, rwb, rrb, p_att);

    // 4. output projection + LN1
    gemm_nn_tf32<<<dim3(EE / 128, (BB * QLEN) / 128), 256>>>(p_att, HD, Wo, EE, p_o, EE, EE, HD, 0);
    add_ln_kernel<<<BB * QLEN, 256>>>(w, p_o, ln1g, ln1b, p_x);

    // 5. FFN + LN2 -> out
    gemm_nn_tf32<<<dim3(FF / 128, (BB * QLEN) / 128), 256>>>(p_x,   EE, W1, FF, p_ffn, FF, FF, EE, 1);
    gemm_nn_tf32<<<dim3(EE / 128, (BB * QLEN) / 128), 256>>>(p_ffn, FF, W2, EE, p_y,   EE, EE, FF, 0);
    add_ln_kernel<<<BB * QLEN, 256>>>(p_y, p_x, ln2g, ln2b, out);
}

// round 5
// speedup vs baseline: 1.3461x; 1.3461x over previous
#include <cuda_runtime.h>
#include <cuda_bf16.h>
#include <math.h>

#define BB 2
#define QLEN 1024
#define MLEN 1024
#define KLEN 2048
#define EE 1024
#define HH 16
#define DH 64
#define HD 1024   // HH*DH
#define FF 4096

// ---------------- scratch ----------------
static __device__ float g_cat[(size_t)BB * KLEN * EE];
static __device__ float g_q  [(size_t)BB * QLEN * HD];   // used as bf16
static __device__ float g_k  [(size_t)BB * KLEN * HD];   // used as bf16
static __device__ float g_v  [(size_t)BB * KLEN * HD];   // used as bf16
static __device__ float g_r  [(size_t)KLEN * HD];        // used as bf16
static __device__ float g_att[(size_t)BB * QLEN * HD];
static __device__ float g_o  [(size_t)BB * QLEN * EE];
static __device__ float g_x  [(size_t)BB * QLEN * EE];
static __device__ float g_ffn[(size_t)BB * QLEN * FF];
static __device__ float g_y  [(size_t)BB * QLEN * EE];

// ---------------- helpers ----------------
__device__ __forceinline__ unsigned f2t(float x) {
    unsigned u; asm("cvt.rna.tf32.f32 %0, %1;" : "=r"(u) : "f"(x)); return u;
}
__device__ __forceinline__ unsigned pack_bf2(float lo, float hi) {
    unsigned u; asm("cvt.rn.bf16x2.f32 %0, %1, %2;" : "=r"(u) : "f"(hi), "f"(lo)); return u;
}
__device__ __forceinline__ void mma8(float* c, const unsigned* a, const unsigned* b) {
    asm volatile("mma.sync.aligned.m16n8k8.row.col.f32.tf32.tf32.f32 "
        "{%0,%1,%2,%3}, {%4,%5,%6,%7}, {%8,%9}, {%0,%1,%2,%3};\n"
        : "+f"(c[0]), "+f"(c[1]), "+f"(c[2]), "+f"(c[3])
        : "r"(a[0]), "r"(a[1]), "r"(a[2]), "r"(a[3]), "r"(b[0]), "r"(b[1]));
}
__device__ __forceinline__ void mma16(float* c, const unsigned* a, const unsigned* b) {
    asm volatile("mma.sync.aligned.m16n8k16.row.col.f32.bf16.bf16.f32 "
        "{%0,%1,%2,%3}, {%4,%5,%6,%7}, {%8,%9}, {%0,%1,%2,%3};\n"
        : "+f"(c[0]), "+f"(c[1]), "+f"(c[2]), "+f"(c[3])
        : "r"(a[0]), "r"(a[1]), "r"(a[2]), "r"(a[3]), "r"(b[0]), "r"(b[1]));
}
__device__ __forceinline__ void cpa16(unsigned saddr, const void* g) {
    asm volatile("cp.async.cg.shared.global [%0], [%1], 16;" :: "r"(saddr), "l"(g));
}
__device__ __forceinline__ void cpa_commit() { asm volatile("cp.async.commit_group;"); }
__device__ __forceinline__ void cpa_waitall() { asm volatile("cp.async.wait_group 0;"); }

// ---------------- cat = concat(member, w) ----------------
__global__ __launch_bounds__(256) void copy_cat_kernel(
    const float4* __restrict__ w, const float4* __restrict__ member, float4* __restrict__ cat)
{
    size_t i = (size_t)blockIdx.x * 256 + threadIdx.x;
    int e4 = (int)(i % (EE / 4));
    size_t t2 = i / (EE / 4);
    int kl = (int)(t2 % KLEN);
    int b  = (int)(t2 / KLEN);
    float4 v;
    if (kl < MLEN) v = member[((size_t)b * MLEN + kl) * (EE / 4) + e4];
    else           v = w[((size_t)b * QLEN + (kl - MLEN)) * (EE / 4) + e4];
    cat[i] = v;
}

// ================= tf32 MMA GEMM, NN; obf=1 writes bf16 =================
__global__ __launch_bounds__(256, 2) void gemm_nn_tf32(
    const float* __restrict__ A, int lda, const float* __restrict__ B, int ldb,
    float* __restrict__ C, int ldc, int N, int K, int relu, int obf)
{
    __shared__ __align__(16) unsigned As[2][128][20];
    __shared__ __align__(16) unsigned Bs[2][16][136];

    const int t = threadIdx.x;
    const int lane = t & 31, warp = t >> 5;
    const int g = lane >> 2, tig = lane & 3;
    const int wm0 = (warp >> 2) * 64, wn0 = (warp & 3) * 32;
    const int m0 = blockIdx.y * 128, n0 = blockIdx.x * 128;

    const int arow = t >> 2,  akc = (t & 3) * 4;
    const int brow = t >> 5,  bnc = (t & 31) * 4;

    float c[4][4][4] = {};

    {
        #pragma unroll
        for (int j = 0; j < 2; j++) {
            int row = arow + 64 * j;
            float4 f = *(const float4*)&A[(size_t)(m0 + row) * lda + akc];
            As[0][row][akc + 0] = f2t(f.x); As[0][row][akc + 1] = f2t(f.y);
            As[0][row][akc + 2] = f2t(f.z); As[0][row][akc + 3] = f2t(f.w);
        }
        #pragma unroll
        for (int j = 0; j < 2; j++) {
            int row = brow + 8 * j;
            int n = n0 + bnc;
            float4 f = make_float4(0.f, 0.f, 0.f, 0.f);
            if (n < N) f = *(const float4*)&B[(size_t)row * ldb + n];
            Bs[0][row][bnc + 0] = f2t(f.x); Bs[0][row][bnc + 1] = f2t(f.y);
            Bs[0][row][bnc + 2] = f2t(f.z); Bs[0][row][bnc + 3] = f2t(f.w);
        }
    }
    __syncthreads();

    const int nk = K / 16;
    int buf = 0;
    for (int kt = 0; kt < nk; kt++) {
        float4 ra[2], rb[2];
        if (kt + 1 < nk) {
            int k0 = (kt + 1) * 16;
            #pragma unroll
            for (int j = 0; j < 2; j++)
                ra[j] = *(const float4*)&A[(size_t)(m0 + arow + 64 * j) * lda + k0 + akc];
            #pragma unroll
            for (int j = 0; j < 2; j++) {
                int n = n0 + bnc;
                rb[j] = make_float4(0.f, 0.f, 0.f, 0.f);
                if (n < N) rb[j] = *(const float4*)&B[(size_t)(k0 + brow + 8 * j) * ldb + n];
            }
        }
        #pragma unroll
        for (int ks = 0; ks < 16; ks += 8) {
            unsigned af[4][4], bf[4][2];
            #pragma unroll
            for (int mi = 0; mi < 4; mi++) {
                int m = wm0 + mi * 16 + g;
                af[mi][0] = As[buf][m][ks + tig];
                af[mi][1] = As[buf][m + 8][ks + tig];
                af[mi][2] = As[buf][m][ks + tig + 4];
                af[mi][3] = As[buf][m + 8][ks + tig + 4];
            }
            #pragma unroll
            for (int ni = 0; ni < 4; ni++) {
                int n = wn0 + ni * 8 + g;
                bf[ni][0] = Bs[buf][ks + tig][n];
                bf[ni][1] = Bs[buf][ks + tig + 4][n];
            }
            #pragma unroll
            for (int mi = 0; mi < 4; mi++)
                #pragma unroll
                for (int ni = 0; ni < 4; ni++)
                    mma8(c[mi][ni], af[mi], bf[ni]);
        }
        if (kt + 1 < nk) {
            int nb = buf ^ 1;
            #pragma unroll
            for (int j = 0; j < 2; j++) {
                int row = arow + 64 * j;
                As[nb][row][akc + 0] = f2t(ra[j].x); As[nb][row][akc + 1] = f2t(ra[j].y);
                As[nb][row][akc + 2] = f2t(ra[j].z); As[nb][row][akc + 3] = f2t(ra[j].w);
            }
            #pragma unroll
            for (int j = 0; j < 2; j++) {
                int row = brow + 8 * j;
                Bs[nb][row][bnc + 0] = f2t(rb[j].x); Bs[nb][row][bnc + 1] = f2t(rb[j].y);
                Bs[nb][row][bnc + 2] = f2t(rb[j].z); Bs[nb][row][bnc + 3] = f2t(rb[j].w);
            }
            __syncthreads();
        }
        buf ^= 1;
    }

    #pragma unroll
    for (int mi = 0; mi < 4; mi++) {
        int row = m0 + wm0 + mi * 16 + g;
        #pragma unroll
        for (int ni = 0; ni < 4; ni++) {
            int col = n0 + wn0 + ni * 8 + 2 * tig;
            if (col < N) {
                float2 v0 = make_float2(c[mi][ni][0], c[mi][ni][1]);
                float2 v1 = make_float2(c[mi][ni][2], c[mi][ni][3]);
                if (relu) {
                    v0.x = fmaxf(v0.x, 0.f); v0.y = fmaxf(v0.y, 0.f);
                    v1.x = fmaxf(v1.x, 0.f); v1.y = fmaxf(v1.y, 0.f);
                }
                if (obf) {
                    unsigned* Cu = (unsigned*)C;
                    Cu[((size_t)row * ldc + col) / 2]       = pack_bf2(v0.x, v0.y);
                    Cu[((size_t)(row + 8) * ldc + col) / 2] = pack_bf2(v1.x, v1.y);
                } else {
                    *(float2*)&C[(size_t)row * ldc + col] = v0;
                    *(float2*)&C[(size_t)(row + 8) * ldc + col] = v1;
                }
            }
        }
    }
}

// ================= bf16 pipelined flash attention with rel-shift =================
// smem layout (bytes): QW 0, QR 18432, K 36864(x2), V 73728(x2), R 110592(256 rows),
// G 147456 (128x264 bf16; P overlays at stride 136), RED 215040 (2x512 f32)
#define QS 36        // word stride (72 bf16)
#define GS 264       // sG stride, bf16
#define PS 68        // P word stride (136 bf16)
#define OFF_QW 0
#define OFF_QR 18432
#define OFF_K  36864
#define OFF_V  73728
#define OFF_R  110592
#define OFF_G  147456
#define OFF_RED 215040
#define FA_SMEM 219136

__global__ __launch_bounds__(256, 1) void flash_attn(
    const __nv_bfloat16* __restrict__ Qb, const __nv_bfloat16* __restrict__ Kb,
    const __nv_bfloat16* __restrict__ Vb, const __nv_bfloat16* __restrict__ Rb,
    const float* __restrict__ rwb, const float* __restrict__ rrb,
    float* __restrict__ Om)
{
    extern __shared__ __align__(16) char smem[];
    unsigned*  uQw = (unsigned*)(smem + OFF_QW);
    unsigned*  uQr = (unsigned*)(smem + OFF_QR);
    unsigned*  uG  = (unsigned*)(smem + OFF_G);
    __nv_bfloat16* hG = (__nv_bfloat16*)(smem + OFF_G);
    float* redM = (float*)(smem + OFF_RED);
    float* redS = redM + 512;
    const unsigned sb = (unsigned)__cvta_generic_to_shared(smem);

    const int t = threadIdx.x;
    const int lane = t & 31, warp = t >> 5;
    const int g = lane >> 2, tig = lane & 3;
    const int wm0 = (warp >> 2) * 64;
    const int wn  = warp & 3;
    const int wn0 = wn * 32;
    const int wn0p = wn * 16;

    const int bh = blockIdx.z, b = bh >> 4, h = bh & 15;
    const int q0 = (gridDim.y - 1 - blockIdx.y) * 128;   // heavy CTAs first
    const int ntiles = q0 / 128 + 9;

    const __nv_bfloat16* gK = Kb + ((size_t)b * KLEN) * HD + h * DH;
    const __nv_bfloat16* gV = Vb + ((size_t)b * KLEN) * HD + h * DH;
    const __nv_bfloat16* gR = Rb + h * DH;

    // ---- prologue: issue cp.async for K/V(0), R(0) ----
    {
        #pragma unroll
        for (int i = 0; i < 4; i++) {
            int id = t + 256 * i, row = id >> 3, ch = id & 7;
            cpa16(sb + OFF_K + row * 144 + ch * 16, gK + (size_t)row * HD + ch * 8);
            cpa16(sb + OFF_V + row * 144 + ch * 16, gV + (size_t)row * HD + ch * 8);
        }
        cpa_commit();
        int j0 = 0 - q0 + (QLEN - 128);
        #pragma unroll
        for (int i = 0; i < 8; i++) {
            int id = t + 256 * i, row = id >> 3, ch = id & 7;
            int j = j0 + row; if (j > KLEN - 1) j = KLEN - 1;
            cpa16(sb + OFF_R + row * 144 + ch * 16, gR + (size_t)j * HD + ch * 8);
        }
        cpa_commit();
    }

    // ---- load Q tile with both biases (bf16) ----
    {
        const __nv_bfloat16* qsrc = Qb + ((size_t)b * QLEN + q0) * HD + h * DH;
        int lr = t >> 1, lc0 = (t & 1) * 32;
        #pragma unroll
        for (int i = 0; i < 8; i++) {
            int c = lc0 + i * 4;
            uint2 u = *(const uint2*)&qsrc[(size_t)lr * HD + c];
            __nv_bfloat162 q01 = *(__nv_bfloat162*)&u.x;
            __nv_bfloat162 q23 = *(__nv_bfloat162*)&u.y;
            float4 bw = *(const float4*)&rwb[h * DH + c];
            float4 br = *(const float4*)&rrb[h * DH + c];
            float f0 = __bfloat162float(q01.x), f1 = __bfloat162float(q01.y);
            float f2 = __bfloat162float(q23.x), f3 = __bfloat162float(q23.y);
            uQw[lr * QS + c / 2]     = pack_bf2(f0 + bw.x, f1 + bw.y);
            uQw[lr * QS + c / 2 + 1] = pack_bf2(f2 + bw.z, f3 + bw.w);
            uQr[lr * QS + c / 2]     = pack_bf2(f0 + br.x, f1 + br.y);
            uQr[lr * QS + c / 2 + 1] = pack_bf2(f2 + br.z, f3 + br.w);
        }
    }

    float o[4][2][4] = {};
    float mrun[4][2], lrun[4][2];
    #pragma unroll
    for (int mi = 0; mi < 4; mi++)
        #pragma unroll
        for (int hh = 0; hh < 2; hh++) { mrun[mi][hh] = -INFINITY; lrun[mi][hh] = 0.f; }

    int buf = 0;
    for (int kt = 0; kt < ntiles; kt++) {
        const int k0 = kt * 128;
        cpa_waitall();
        __syncthreads();

        // prefetch K/V for next tile into alternate buffer
        if (kt + 1 < ntiles) {
            const __nv_bfloat16* nK = gK + (size_t)(k0 + 128) * HD;
            const __nv_bfloat16* nV = gV + (size_t)(k0 + 128) * HD;
            unsigned kb = OFF_K + (buf ^ 1) * 18432, vb2 = OFF_V + (buf ^ 1) * 18432;
            #pragma unroll
            for (int i = 0; i < 4; i++) {
                int id = t + 256 * i, row = id >> 3, ch = id & 7;
                cpa16(sb + kb + row * 144 + ch * 16, nK + (size_t)row * HD + ch * 8);
                cpa16(sb + vb2 + row * 144 + ch * 16, nV + (size_t)row * HD + ch * 8);
            }
            cpa_commit();
        }

        // ---- AC MMA: acc = (Q+rwb) @ K^T ----
        float acc[4][4][4] = {};
        {
            const unsigned* uK = (const unsigned*)(smem + OFF_K + buf * 18432);
            #pragma unroll
            for (int ks = 0; ks < 4; ks++) {
                unsigned af[4][4], bf[4][2];
                #pragma unroll
                for (int mi = 0; mi < 4; mi++) {
                    int m = wm0 + mi * 16 + g;
                    af[mi][0] = uQw[m * QS + ks * 8 + tig];
                    af[mi][1] = uQw[(m + 8) * QS + ks * 8 + tig];
                    af[mi][2] = uQw[m * QS + ks * 8 + tig + 4];
                    af[mi][3] = uQw[(m + 8) * QS + ks * 8 + tig + 4];
                }
                #pragma unroll
                for (int ni = 0; ni < 4; ni++) {
                    int n = wn0 + ni * 8 + g;
                    bf[ni][0] = uK[n * QS + ks * 8 + tig];
                    bf[ni][1] = uK[n * QS + ks * 8 + tig + 4];
                }
                #pragma unroll
                for (int mi = 0; mi < 4; mi++)
                    #pragma unroll
                    for (int ni = 0; ni < 4; ni++)
                        mma16(acc[mi][ni], af[mi], bf[ni]);
            }
        }

        // ---- G MMA: 128x256 band, two column halves, write bf16 to sG ----
        {
            const unsigned* uR = (const unsigned*)(smem + OFF_R);
            #pragma unroll
            for (int h2 = 0; h2 < 2; h2++) {
                float ga[4][4][4] = {};
                #pragma unroll
                for (int ks = 0; ks < 4; ks++) {
                    unsigned af[4][4], bf[4][2];
                    #pragma unroll
                    for (int mi = 0; mi < 4; mi++) {
                        int m = wm0 + mi * 16 + g;
                        af[mi][0] = uQr[m * QS + ks * 8 + tig];
                        af[mi][1] = uQr[(m + 8) * QS + ks * 8 + tig];
                        af[mi][2] = uQr[m * QS + ks * 8 + tig + 4];
                        af[mi][3] = uQr[(m + 8) * QS + ks * 8 + tig + 4];
                    }
                    #pragma unroll
                    for (int ni = 0; ni < 4; ni++) {
                        int n = h2 * 128 + wn0 + ni * 8 + g;
                        bf[ni][0] = uR[n * QS + ks * 8 + tig];
                        bf[ni][1] = uR[n * QS + ks * 8 + tig + 4];
                    }
                    #pragma unroll
                    for (int mi = 0; mi < 4; mi++)
                        #pragma unroll
                        for (int ni = 0; ni < 4; ni++)
                            mma16(ga[mi][ni], af[mi], bf[ni]);
                }
                #pragma unroll
                for (int mi = 0; mi < 4; mi++)
                    #pragma unroll
                    for (int ni = 0; ni < 4; ni++)
                        #pragma unroll
                        for (int hh = 0; hh < 2; hh++) {
                            int r = wm0 + mi * 16 + g + 8 * hh;
                            int col = h2 * 128 + wn0 + ni * 8 + 2 * tig;
                            uG[(r * GS + col) / 2] = pack_bf2(ga[mi][ni][2 * hh], ga[mi][ni][2 * hh + 1]);
                        }
            }
        }
        __syncthreads();   // G visible; sR fully consumed

        // prefetch R for next tile
        if (kt + 1 < ntiles) {
            int j0n = (k0 + 128) - q0 + (QLEN - 128);
            #pragma unroll
            for (int i = 0; i < 8; i++) {
                int id = t + 256 * i, row = id >> 3, ch = id & 7;
                int j = j0n + row; if (j > KLEN - 1) j = KLEN - 1;
                cpa16(sb + OFF_R + row * 144 + ch * 16, gR + (size_t)j * HD + ch * 8);
            }
            cpa_commit();
        }

        // ---- gather shifted BD + mask + scale ----
        #pragma unroll
        for (int mi = 0; mi < 4; mi++)
            #pragma unroll
            for (int ni = 0; ni < 4; ni++)
                #pragma unroll
                for (int hh = 0; hh < 2; hh++)
                    #pragma unroll
                    for (int e = 0; e < 2; e++) {
                        int r = wm0 + mi * 16 + g + 8 * hh;
                        int col = wn0 + ni * 8 + 2 * tig + e;
                        float s = acc[mi][ni][2 * hh + e]
                                + __bfloat162float(hG[r * GS + (col - r + 127)]);
                        acc[mi][ni][2 * hh + e] =
                            ((k0 + col) <= (q0 + r) + MLEN) ? s * 0.03125f : -1e30f;
                    }

        // ---- warp-level softmax stats ----
        float mw[4][2];
        #pragma unroll
        for (int mi = 0; mi < 4; mi++)
            #pragma unroll
            for (int hh = 0; hh < 2; hh++) {
                float m8 = -INFINITY;
                #pragma unroll
                for (int ni = 0; ni < 4; ni++) {
                    m8 = fmaxf(m8, fmaxf(acc[mi][ni][2 * hh], acc[mi][ni][2 * hh + 1]));
                }
                m8 = fmaxf(m8, __shfl_xor_sync(0xffffffffu, m8, 1));
                m8 = fmaxf(m8, __shfl_xor_sync(0xffffffffu, m8, 2));
                mw[mi][hh] = m8;
                float sw = 0.f;
                #pragma unroll
                for (int ni = 0; ni < 4; ni++)
                    #pragma unroll
                    for (int e = 0; e < 2; e++) {
                        float p = __expf(acc[mi][ni][2 * hh + e] - m8);
                        acc[mi][ni][2 * hh + e] = p;
                        sw += p;
                    }
                sw += __shfl_xor_sync(0xffffffffu, sw, 1);
                sw += __shfl_xor_sync(0xffffffffu, sw, 2);
                if (tig == 0) {
                    int r = wm0 + mi * 16 + g + 8 * hh;
                    redM[wn * 128 + r] = m8;
                    redS[wn * 128 + r] = sw;
                }
            }
        __syncthreads();

        // ---- combine across warps, rescale, write P ----
        float fsc[4][2];
        #pragma unroll
        for (int mi = 0; mi < 4; mi++)
            #pragma unroll
            for (int hh = 0; hh < 2; hh++) {
                int r = wm0 + mi * 16 + g + 8 * hh;
                float m0v = redM[r], m1v = redM[128 + r], m2v = redM[256 + r], m3v = redM[384 + r];
                float mnew = fmaxf(mrun[mi][hh],
                              fmaxf(fmaxf(m0v, m1v), fmaxf(m2v, m3v)));
                float ladd = redS[r] * __expf(m0v - mnew) + redS[128 + r] * __expf(m1v - mnew)
                           + redS[256 + r] * __expf(m2v - mnew) + redS[384 + r] * __expf(m3v - mnew);
                float alpha = __expf(mrun[mi][hh] - mnew);
                lrun[mi][hh] = lrun[mi][hh] * alpha + ladd;
                mrun[mi][hh] = mnew;
                fsc[mi][hh] = __expf(mw[mi][hh] - mnew);
                #pragma unroll
                for (int ni2 = 0; ni2 < 2; ni2++) {
                    o[mi][ni2][2 * hh]     *= alpha;
                    o[mi][ni2][2 * hh + 1] *= alpha;
                }
            }
        #pragma unroll
        for (int mi = 0; mi < 4; mi++)
            #pragma unroll
            for (int ni = 0; ni < 4; ni++)
                #pragma unroll
                for (int hh = 0; hh < 2; hh++) {
                    int r = wm0 + mi * 16 + g + 8 * hh;
                    int col = wn0 + ni * 8 + 2 * tig;
                    uG[r * PS + col / 2] = pack_bf2(
                        acc[mi][ni][2 * hh] * fsc[mi][hh],
                        acc[mi][ni][2 * hh + 1] * fsc[mi][hh]);
                }
        __syncthreads();   // P visible

        // ---- PV MMA: O += P @ V ----
        {
            const unsigned short* hV = (const unsigned short*)(smem + OFF_V + buf * 18432);
            #pragma unroll
            for (int ks = 0; ks < 8; ks++) {
                unsigned af[4][4], bf[2][2];
                #pragma unroll
                for (int mi = 0; mi < 4; mi++) {
                    int m = wm0 + mi * 16 + g;
                    af[mi][0] = uG[m * PS + ks * 8 + tig];
                    af[mi][1] = uG[(m + 8) * PS + ks * 8 + tig];
                    af[mi][2] = uG[m * PS + ks * 8 + tig + 4];
                    af[mi][3] = uG[(m + 8) * PS + ks * 8 + tig + 4];
                }
                #pragma unroll
                for (int ni2 = 0; ni2 < 2; ni2++) {
                    int n = wn0p + ni2 * 8 + g;
                    unsigned lo0 = hV[(ks * 16 + 2 * tig) * 72 + n];
                    unsigned hi0 = hV[(ks * 16 + 2 * tig + 1) * 72 + n];
                    unsigned lo1 = hV[(ks * 16 + 2 * tig + 8) * 72 + n];
                    unsigned hi1 = hV[(ks * 16 + 2 * tig + 9) * 72 + n];
                    bf[ni2][0] = lo0 | (hi0 << 16);
                    bf[ni2][1] = lo1 | (hi1 << 16);
                }
                #pragma unroll
                for (int mi = 0; mi < 4; mi++)
                    #pragma unroll
                    for (int ni2 = 0; ni2 < 2; ni2++)
                        mma16(o[mi][ni2], af[mi], bf[ni2]);
            }
        }
        buf ^= 1;
    }

    // ---- epilogue: O /= l ----
    #pragma unroll
    for (int mi = 0; mi < 4; mi++)
        #pragma unroll
        for (int ni2 = 0; ni2 < 2; ni2++)
            #pragma unroll
            for (int hh = 0; hh < 2; hh++) {
                int r = wm0 + mi * 16 + g + 8 * hh;
                int d = wn0p + ni2 * 8 + 2 * tig;
                float inv = 1.0f / lrun[mi][hh];
                *(float2*)&Om[((size_t)b * QLEN + q0 + r) * HD + h * DH + d] =
                    make_float2(o[mi][ni2][2 * hh] * inv, o[mi][ni2][2 * hh + 1] * inv);
            }
}

// ---------------- out = LayerNorm(a + b), rows of EE ----------------
__global__ __launch_bounds__(256) void add_ln_kernel(
    const float* __restrict__ A, const float* __restrict__ Bv,
    const float* __restrict__ gamma, const float* __restrict__ beta,
    float* __restrict__ out)
{
    __shared__ float red[256];
    const size_t row = blockIdx.x;
    const int t = threadIdx.x;
    float4 va = ((const float4*)(A + row * EE))[t];
    float4 vb = ((const float4*)(Bv + row * EE))[t];
    float4 v = make_float4(va.x + vb.x, va.y + vb.y, va.z + vb.z, va.w + vb.w);

    red[t] = v.x + v.y + v.z + v.w; __syncthreads();
    for (int s = 128; s > 0; s >>= 1) { if (t < s) red[t] += red[t + s]; __syncthreads(); }
    const float mean = red[0] * (1.0f / EE); __syncthreads();

    float dx = v.x - mean, dy = v.y - mean, dz = v.z - mean, dw = v.w - mean;
    red[t] = dx * dx + dy * dy + dz * dz + dw * dw; __syncthreads();
    for (int s = 128; s > 0; s >>= 1) { if (t < s) red[t] += red[t + s]; __syncthreads(); }
    const float inv = rsqrtf(red[0] * (1.0f / EE) + 1e-3f);

    float4 gm = ((const float4*)gamma)[t];
    float4 bt = ((const float4*)beta)[t];
    float4 o;
    o.x = dx * inv * gm.x + bt.x; o.y = dy * inv * gm.y + bt.y;
    o.z = dz * inv * gm.z + bt.z; o.w = dw * inv * gm.w + bt.w;
    ((float4*)(out + row * EE))[t] = o;
}

// ---------------- launch ----------------
extern "C" void kernel_launch(void* const* d_in, const int* in_sizes, int n_in,
                              void* d_out, int out_size)
{
    const float* w      = (const float*)d_in[0];
    const float* r      = (const float*)d_in[1];
    const float* member = (const float*)d_in[2];
    const float* Wq  = (const float*)d_in[4];
    const float* Wk  = (const float*)d_in[5];
    const float* Wv  = (const float*)d_in[6];
    const float* Wr  = (const float*)d_in[7];
    const float* Wo  = (const float*)d_in[8];
    const float* rwb = (const float*)d_in[9];
    const float* rrb = (const float*)d_in[10];
    const float* ln1g = (const float*)d_in[11];
    const float* ln1b = (const float*)d_in[12];
    const float* W1  = (const float*)d_in[13];
    const float* W2  = (const float*)d_in[14];
    const float* ln2g = (const float*)d_in[15];
    const float* ln2b = (const float*)d_in[16];
    float* out = (float*)d_out;

    static float *p_cat = nullptr, *p_q, *p_k, *p_v, *p_r,
                 *p_att, *p_o, *p_x, *p_ffn, *p_y;
    if (!p_cat) {
        cudaGetSymbolAddress((void**)&p_cat, g_cat);
        cudaGetSymbolAddress((void**)&p_q,   g_q);
        cudaGetSymbolAddress((void**)&p_k,   g_k);
        cudaGetSymbolAddress((void**)&p_v,   g_v);
        cudaGetSymbolAddress((void**)&p_r,   g_r);
        cudaGetSymbolAddress((void**)&p_att, g_att);
        cudaGetSymbolAddress((void**)&p_o,   g_o);
        cudaGetSymbolAddress((void**)&p_x,   g_x);
        cudaGetSymbolAddress((void**)&p_ffn, g_ffn);
        cudaGetSymbolAddress((void**)&p_y,   g_y);
        cudaFuncSetAttribute(flash_attn, cudaFuncAttributeMaxDynamicSharedMemorySize, FA_SMEM);
    }

    // 1. cat
    copy_cat_kernel<<<(BB * KLEN * EE / 4) / 256, 256>>>(
        (const float4*)w, (const float4*)member, (float4*)p_cat);

    // 2. projections (tf32 MMA, bf16 output for attention operands)
    gemm_nn_tf32<<<dim3(HD / 128, (BB * QLEN) / 128), 256>>>(w,     EE, Wq, HD, p_q, HD, HD, EE, 0, 1);
    gemm_nn_tf32<<<dim3(HD / 128, (BB * KLEN) / 128), 256>>>(p_cat, EE, Wk, HD, p_k, HD, HD, EE, 0, 1);
    gemm_nn_tf32<<<dim3(HD / 128, (BB * KLEN) / 128), 256>>>(p_cat, EE, Wv, HD, p_v, HD, HD, EE, 0, 1);
    gemm_nn_tf32<<<dim3(HD / 128, KLEN / 128),        256>>>(r,     EE, Wr, HD, p_r, HD, HD, EE, 0, 1);

    // 3. fused attention (AC + shifted BD + softmax + PV), bf16 MMA + cp.async
    flash_attn<<<dim3(1, QLEN / 128, BB * HH), 256, FA_SMEM>>>(
        (const __nv_bfloat16*)p_q, (const __nv_bfloat16*)p_k,
        (const __nv_bfloat16*)p_v, (const __nv_bfloat16*)p_r,
        rwb, rrb, p_att);

    // 4. output projection + LN1
    gemm_nn_tf32<<<dim3(EE / 128, (BB * QLEN) / 128), 256>>>(p_att, HD, Wo, EE, p_o, EE, EE, HD, 0, 0);
    add_ln_kernel<<<BB * QLEN, 256>>>(w, p_o, ln1g, ln1b, p_x);

    // 5. FFN + LN2 -> out
    gemm_nn_tf32<<<dim3(FF / 128, (BB * QLEN) / 128), 256>>>(p_x,   EE, W1, FF, p_ffn, FF, FF, EE, 1, 0);
    gemm_nn_tf32<<<dim3(EE / 128, (BB * QLEN) / 128), 256>>>(p_ffn, FF, W2, EE, p_y,   EE, EE, FF, 0, 0);
    add_ln_kernel<<<BB * QLEN, 256>>>(p_y, p_x, ln2g, ln2b, out);
}